// round 6
// baseline (speedup 1.0000x reference)
#include <cuda_runtime.h>
#include <mma.h>

using namespace nvcuda;

#define NQ_MAX 50000
#define NC 128
#define NG 8
#define NS 16

// Padded by 128 rows: partial-tile wmma stores at the M edge write into the
// pad instead of the neighboring buffer.
__device__ float g_q[(NQ_MAX + 128) * NC];
__device__ float g_k[(NQ_MAX + 128) * NC];
__device__ float g_v[(NQ_MAX + 128) * NC];
__device__ float g_ksum[(NQ_MAX + 128) * NG];   // per (key, group) raw-K sums

__device__ __forceinline__ float to_tf32(float x) {
    float r;
    asm("cvt.rna.tf32.f32 %0, %1;" : "=f"(r) : "f"(x));
    return r;
}

// ---------------------------------------------------------------------------
// Projection GEMM (tf32 tensor cores) — R4 version (known 71us).
// Y[m,c] = sum_k X[m,k] * W[c,k]   (biases folded into attn kernel)
// Block tile 128x128, BK=32, 8 warps: 4(M) x 2(N), warp tile 32x64.
// ---------------------------------------------------------------------------
#define LDA 36

__global__ void __launch_bounds__(256) proj_kernel(
    const float* __restrict__ x, const float* __restrict__ x2,
    const float* __restrict__ Wq, const float* __restrict__ Wk,
    const float* __restrict__ Wv,
    int n, int n2)
{
    const float *X, *W;
    float* Y;
    int M;
    if (blockIdx.y == 0)      { X = x;  W = Wq; Y = g_q; M = n;  }
    else if (blockIdx.y == 1) { X = x2; W = Wk; Y = g_k; M = n2; }
    else                      { X = x2; W = Wv; Y = g_v; M = n2; }

    __shared__ float As[128 * LDA];
    __shared__ float Bs[128 * LDA];

    const int t = threadIdx.x;
    const int block_m = blockIdx.x * 128;
    if (block_m >= M) return;

    const int warp = t >> 5;
    const int wm = (warp & 3) * 32;
    const int wn = (warp >> 2) * 64;

    wmma::fragment<wmma::accumulator, 16, 16, 8, float> acc[2][4];
#pragma unroll
    for (int i = 0; i < 2; i++)
#pragma unroll
        for (int j = 0; j < 4; j++) wmma::fill_fragment(acc[i][j], 0.0f);

    for (int k0 = 0; k0 < 128; k0 += 32) {
#pragma unroll
        for (int it = 0; it < 4; it++) {
            int lin = it * 256 + t;
            int r = lin >> 3;
            int c4 = (lin & 7) << 2;
            int gr = block_m + r;
            float4 xv = make_float4(0.f, 0.f, 0.f, 0.f);
            if (gr < M) xv = *(const float4*)(X + (size_t)gr * 128 + k0 + c4);
            As[r * LDA + c4 + 0] = to_tf32(xv.x);
            As[r * LDA + c4 + 1] = to_tf32(xv.y);
            As[r * LDA + c4 + 2] = to_tf32(xv.z);
            As[r * LDA + c4 + 3] = to_tf32(xv.w);
            float4 wv = *(const float4*)(W + (size_t)r * 128 + k0 + c4);
            Bs[r * LDA + c4 + 0] = to_tf32(wv.x);
            Bs[r * LDA + c4 + 1] = to_tf32(wv.y);
            Bs[r * LDA + c4 + 2] = to_tf32(wv.z);
            Bs[r * LDA + c4 + 3] = to_tf32(wv.w);
        }
        __syncthreads();

#pragma unroll
        for (int kk = 0; kk < 32; kk += 8) {
            wmma::fragment<wmma::matrix_a, 16, 16, 8, wmma::precision::tf32, wmma::row_major> a[2];
            wmma::fragment<wmma::matrix_b, 16, 16, 8, wmma::precision::tf32, wmma::col_major> b[4];
#pragma unroll
            for (int i = 0; i < 2; i++)
                wmma::load_matrix_sync(a[i], As + (wm + i * 16) * LDA + kk, LDA);
#pragma unroll
            for (int j = 0; j < 4; j++)
                wmma::load_matrix_sync(b[j], Bs + (wn + j * 16) * LDA + kk, LDA);
#pragma unroll
            for (int i = 0; i < 2; i++)
#pragma unroll
                for (int j = 0; j < 4; j++)
                    wmma::mma_sync(acc[i][j], a[i], b[j], acc[i][j]);
        }
        __syncthreads();
    }

#pragma unroll
    for (int i = 0; i < 2; i++)
#pragma unroll
        for (int j = 0; j < 4; j++)
            wmma::store_matrix_sync(
                Y + (size_t)(block_m + wm + i * 16) * 128 + wn + j * 16,
                acc[i][j], 128, wmma::mem_row_major);
}

// ---------------------------------------------------------------------------
// Per-(key, group) raw-K channel sums: g_ksum[j*8+g] = sum_{c in g} g_k[j][c].
// One thread per (j,g); 8 consecutive threads cover one 512B row (coalesced).
// ---------------------------------------------------------------------------
__global__ void __launch_bounds__(256) ksum_kernel(int n2)
{
    const int tid = blockIdx.x * 256 + threadIdx.x;
    if (tid >= n2 * NG) return;
    const int j = tid >> 3;
    const int g = tid & 7;
    const float4* kp = (const float4*)(g_k + (size_t)j * 128 + g * 16);
    float4 a = kp[0], b = kp[1], c = kp[2], d = kp[3];
    float s = (a.x + a.y + a.z + a.w) + (b.x + b.y + b.z + b.w)
            + (c.x + c.y + c.z + c.w) + (d.x + d.y + d.z + d.w);
    g_ksum[tid] = s;
}

// ---------------------------------------------------------------------------
// Fused gather + positional MLP + grouped attention.
// Thread-per-(query, group): lane = qlocal*8 + g; warp covers 4 queries.
// Each thread owns all 16 channels of its group -> local dot products,
// local softmax, ZERO shuffles. MLP warp-issues amortized over 4 queries.
// logit = 0.25*(kq + prq*ks + beta + prq*Bg + prk*(qs + 16*prq))
//   kq = sum_g k_raw*q', ks = g_ksum (precomputed), qs = sum_g q',
//   beta = sum_g bk*q', Bg = sum_g bk.  out = o/d + bv.
// ---------------------------------------------------------------------------
__global__ void __launch_bounds__(256) attn_kernel(
    const float* __restrict__ p, const float* __restrict__ p2,
    const int* __restrict__ idx,
    const float* __restrict__ bq, const float* __restrict__ bk,
    const float* __restrict__ bv,
    const float* __restrict__ W1, const float* __restrict__ b1,
    const float* __restrict__ bng, const float* __restrict__ bnb,
    const float* __restrict__ bnm, const float* __restrict__ bnv,
    const float* __restrict__ W2, const float* __restrict__ b2,
    float* __restrict__ out, int n)
{
    __shared__ float sA[9];
    __shared__ float sc[3];
    __shared__ float sW2[16][3];
    __shared__ float sb2[16];
    __shared__ float sBg[8];

    const int t = threadIdx.x;
    if (t < 9) {
        int r = t / 3;
        float s = bng[r] * rsqrtf(bnv[r] + 1e-5f);
        sA[t] = s * W1[t];
    }
    if (t < 3) sc[t] = bng[t] * rsqrtf(bnv[t] + 1e-5f) * (b1[t] - bnm[t]) + bnb[t];
    if (t < 48) sW2[t / 3][t % 3] = W2[t];
    if (t < 16) sb2[t] = b2[t];
    if (t < 8) {
        float s = 0.f;
#pragma unroll
        for (int c = 0; c < 16; c++) s += bk[t * 16 + c];
        sBg[t] = s;
    }
    __syncthreads();

    const int lane = t & 31;
    const int warp = t >> 5;
    const int g = lane & 7;
    const int i = blockIdx.x * 32 + warp * 4 + (lane >> 3);
    if (i >= n) return;

    const float w2q0 = sW2[g][0], w2q1 = sW2[g][1], w2q2 = sW2[g][2], b2q = sb2[g];
    const float w2k0 = sW2[8 + g][0], w2k1 = sW2[8 + g][1], w2k2 = sW2[8 + g][2], b2k = sb2[8 + g];
    const float Bg = sBg[g];

    // q' = q_raw + bq for this thread's 16 channels
    float4 q[4];
    float qs = 0.f, beta = 0.f;
    {
        const float4* qp  = (const float4*)(g_q + (size_t)i * 128 + g * 16);
        const float4* bqp = (const float4*)(bq + g * 16);
        const float4* bkp = (const float4*)(bk + g * 16);
#pragma unroll
        for (int c = 0; c < 4; c++) {
            float4 qv = qp[c], bqv = bqp[c], bkv = bkp[c];
            qv.x += bqv.x; qv.y += bqv.y; qv.z += bqv.z; qv.w += bqv.w;
            q[c] = qv;
            qs += qv.x + qv.y + qv.z + qv.w;
            beta += bkv.x * qv.x + bkv.y * qv.y + bkv.z * qv.z + bkv.w * qv.w;
        }
    }

    const float px = p[i * 3 + 0], py = p[i * 3 + 1], pz = p[i * 3 + 2];

    int nb[16];
    {
        const int4* ip = (const int4*)(idx + (size_t)i * 16);
#pragma unroll
        for (int s4 = 0; s4 < 4; s4++) {
            int4 v = ip[s4];
            nb[s4 * 4 + 0] = v.x; nb[s4 * 4 + 1] = v.y;
            nb[s4 * 4 + 2] = v.z; nb[s4 * 4 + 3] = v.w;
        }
    }

    const float base = beta;   // constant part of logit pre-scale

    float logit[16];
#pragma unroll
    for (int s = 0; s < 16; s++) {
        const int j = nb[s];
        const float4* kp = (const float4*)(g_k + (size_t)j * 128 + g * 16);
        float kq = 0.f;
#pragma unroll
        for (int c = 0; c < 4; c++) {
            const float4 kv = kp[c];
            kq = fmaf(kv.x, q[c].x, kq);
            kq = fmaf(kv.y, q[c].y, kq);
            kq = fmaf(kv.z, q[c].z, kq);
            kq = fmaf(kv.w, q[c].w, kq);
        }
        const float ks = g_ksum[j * NG + g];

        const float rx = p2[j * 3 + 0] - px;
        const float ry = p2[j * 3 + 1] - py;
        const float rz = p2[j * 3 + 2] - pz;
        const float h0 = fmaxf(fmaf(sA[0], rx, fmaf(sA[1], ry, fmaf(sA[2], rz, sc[0]))), 0.f);
        const float h1 = fmaxf(fmaf(sA[3], rx, fmaf(sA[4], ry, fmaf(sA[5], rz, sc[1]))), 0.f);
        const float h2 = fmaxf(fmaf(sA[6], rx, fmaf(sA[7], ry, fmaf(sA[8], rz, sc[2]))), 0.f);
        const float prq = fmaf(w2q0, h0, fmaf(w2q1, h1, fmaf(w2q2, h2, b2q)));
        const float prk = fmaf(w2k0, h0, fmaf(w2k1, h1, fmaf(w2k2, h2, b2k)));

        logit[s] = 0.25f * (kq + base + prq * (ks + Bg) + prk * fmaf(16.f, prq, qs));
    }

    float mx = logit[0];
#pragma unroll
    for (int s = 1; s < 16; s++) mx = fmaxf(mx, logit[s]);
    float denom = 0.f;
#pragma unroll
    for (int s = 0; s < 16; s++) {
        logit[s] = __expf(logit[s] - mx);
        denom += logit[s];
    }
    const float inv = 1.f / denom;

    float4 o[4];
#pragma unroll
    for (int c = 0; c < 4; c++) o[c] = make_float4(0.f, 0.f, 0.f, 0.f);

#pragma unroll
    for (int s = 0; s < 16; s++) {
        const float w = logit[s] * inv;
        const float4* vp = (const float4*)(g_v + (size_t)nb[s] * 128 + g * 16);
#pragma unroll
        for (int c = 0; c < 4; c++) {
            const float4 vv = vp[c];
            o[c].x = fmaf(w, vv.x, o[c].x);
            o[c].y = fmaf(w, vv.y, o[c].y);
            o[c].z = fmaf(w, vv.z, o[c].z);
            o[c].w = fmaf(w, vv.w, o[c].w);
        }
    }

    {
        const float4* bvp = (const float4*)(bv + g * 16);
        float4* op = (float4*)(out + (size_t)i * 128 + g * 16);
#pragma unroll
        for (int c = 0; c < 4; c++) {
            float4 bvv = bvp[c];
            float4 ov = o[c];
            ov.x += bvv.x; ov.y += bvv.y; ov.z += bvv.z; ov.w += bvv.w;
            op[c] = ov;
        }
    }
}

extern "C" void kernel_launch(void* const* d_in, const int* in_sizes, int n_in,
                              void* d_out, int out_size)
{
    const float* p   = (const float*)d_in[0];
    const float* x   = (const float*)d_in[1];
    const float* p2  = (const float*)d_in[2];
    const float* x2  = (const float*)d_in[3];
    const int*   idx = (const int*)d_in[4];
    const float* Wq  = (const float*)d_in[5];
    const float* bq  = (const float*)d_in[6];
    const float* Wk  = (const float*)d_in[7];
    const float* bk  = (const float*)d_in[8];
    const float* Wv  = (const float*)d_in[9];
    const float* bv  = (const float*)d_in[10];
    const float* W1  = (const float*)d_in[11];
    const float* b1  = (const float*)d_in[12];
    const float* bng = (const float*)d_in[13];
    const float* bnb = (const float*)d_in[14];
    const float* bnm = (const float*)d_in[15];
    const float* bnv = (const float*)d_in[16];
    const float* W2  = (const float*)d_in[17];
    const float* b2  = (const float*)d_in[18];
    float* out = (float*)d_out;

    const int n  = in_sizes[1] / NC;
    const int n2 = in_sizes[3] / NC;
    const int mmax = n > n2 ? n : n2;

    dim3 pg((mmax + 127) / 128, 3);
    proj_kernel<<<pg, 256>>>(x, x2, Wq, Wk, Wv, n, n2);
    ksum_kernel<<<(n2 * NG + 255) / 256, 256>>>(n2);
    attn_kernel<<<(n + 31) / 32, 256>>>(p, p2, idx, bq, bk, bv,
                                        W1, b1, bng, bnb, bnm, bnv,
                                        W2, b2, out, n);
}

// round 7
// speedup vs baseline: 1.1566x; 1.1566x over previous
#include <cuda_runtime.h>
#include <mma.h>

using namespace nvcuda;

#define NQ_MAX 50000
#define NC 128
#define NG 8
#define NS 16

// Padded by 128 rows: partial-tile wmma stores at the M edge write into the
// pad instead of the neighboring buffer.
__device__ float g_q[(NQ_MAX + 128) * NC];
__device__ float g_k[(NQ_MAX + 128) * NC];
__device__ float g_v[(NQ_MAX + 128) * NC];

__device__ __forceinline__ float to_tf32(float x) {
    float r;
    asm("cvt.rna.tf32.f32 %0, %1;" : "=f"(r) : "f"(x));
    return r;
}

__device__ __forceinline__ void cp16(unsigned dst, const void* src, bool pred) {
    asm volatile("cp.async.ca.shared.global [%0], [%1], 16, %2;"
                 :: "r"(dst), "l"(src), "r"(pred ? 16 : 0));
}

// ---------------------------------------------------------------------------
// Projection GEMM (tf32 tensor cores), cp.async double-buffered.
// Y[m,c] = sum_k X[m,k] * W[c,k]   (biases folded into attn kernel)
// Block tile 128x128, BK=16 (8 stages), 8 warps: 4(M) x 2(N), warp 32x64.
// fp32 -> tf32 (rna) conversion happens at fragment-register level.
// ---------------------------------------------------------------------------
#define BK 16
#define LDK 24   // row pitch in floats: 16 data + 8 pad = 96 bytes (16B-mult)

__global__ void __launch_bounds__(256) proj_kernel(
    const float* __restrict__ x, const float* __restrict__ x2,
    const float* __restrict__ Wq, const float* __restrict__ Wk,
    const float* __restrict__ Wv,
    int n, int n2)
{
    const float *X, *W;
    float* Y;
    int M;
    if (blockIdx.y == 0)      { X = x;  W = Wq; Y = g_q; M = n;  }
    else if (blockIdx.y == 1) { X = x2; W = Wk; Y = g_k; M = n2; }
    else                      { X = x2; W = Wv; Y = g_v; M = n2; }

    __shared__ float As[2][128 * LDK];
    __shared__ float Bs[2][128 * LDK];

    const int t = threadIdx.x;
    const int block_m = blockIdx.x * 128;
    if (block_m >= M) return;

    const int warp = t >> 5;
    const int wm = (warp & 3) * 32;
    const int wn = (warp >> 2) * 64;

    const unsigned sA0 = (unsigned)__cvta_generic_to_shared(&As[0][0]);
    const unsigned sB0 = (unsigned)__cvta_generic_to_shared(&Bs[0][0]);

    // Per-thread copy slots: 512 float4 per array per stage, 256 threads -> 2 each.
    const int r0_ = t >> 2;              // 0..63
    const int c4_ = (t & 3) << 2;        // 0,4,8,12

#define ISSUE_STAGE(K0, BUF)                                                   \
    {                                                                          \
        _Pragma("unroll")                                                      \
        for (int it = 0; it < 2; it++) {                                       \
            int r = it * 64 + r0_;                                             \
            int gr = block_m + r;                                              \
            unsigned off = (unsigned)(((BUF) * 128 * LDK + r * LDK + c4_) * 4);\
            cp16(sA0 + off, X + (size_t)gr * 128 + (K0) + c4_, gr < M);        \
            cp16(sB0 + off, W + (size_t)r * 128 + (K0) + c4_, true);           \
        }                                                                      \
        asm volatile("cp.async.commit_group;");                                \
    }

    wmma::fragment<wmma::accumulator, 16, 16, 8, float> acc[2][4];
#pragma unroll
    for (int i = 0; i < 2; i++)
#pragma unroll
        for (int j = 0; j < 4; j++) wmma::fill_fragment(acc[i][j], 0.0f);

    ISSUE_STAGE(0, 0);

#pragma unroll
    for (int s = 0; s < 8; s++) {
        if (s < 7) {
            ISSUE_STAGE((s + 1) * BK, (s + 1) & 1);
            asm volatile("cp.async.wait_group 1;");
        } else {
            asm volatile("cp.async.wait_group 0;");
        }
        __syncthreads();

        const int b = s & 1;
#pragma unroll
        for (int kk = 0; kk < BK; kk += 8) {
            wmma::fragment<wmma::matrix_a, 16, 16, 8, wmma::precision::tf32, wmma::row_major> af[2];
            wmma::fragment<wmma::matrix_b, 16, 16, 8, wmma::precision::tf32, wmma::col_major> bf[4];
#pragma unroll
            for (int i = 0; i < 2; i++) {
                wmma::load_matrix_sync(af[i], &As[b][(wm + i * 16) * LDK + kk], LDK);
#pragma unroll
                for (int e = 0; e < af[i].num_elements; e++)
                    af[i].x[e] = to_tf32(af[i].x[e]);
            }
#pragma unroll
            for (int j = 0; j < 4; j++) {
                wmma::load_matrix_sync(bf[j], &Bs[b][(wn + j * 16) * LDK + kk], LDK);
#pragma unroll
                for (int e = 0; e < bf[j].num_elements; e++)
                    bf[j].x[e] = to_tf32(bf[j].x[e]);
            }
#pragma unroll
            for (int i = 0; i < 2; i++)
#pragma unroll
                for (int j = 0; j < 4; j++)
                    wmma::mma_sync(acc[i][j], af[i], bf[j], acc[i][j]);
        }
        __syncthreads();
    }

#pragma unroll
    for (int i = 0; i < 2; i++)
#pragma unroll
        for (int j = 0; j < 4; j++)
            wmma::store_matrix_sync(
                Y + (size_t)(block_m + wm + i * 16) * 128 + wn + j * 16,
                acc[i][j], 128, wmma::mem_row_major);
}

// ---------------------------------------------------------------------------
// Fused gather + positional MLP + grouped attention (R4 version, 91.7us).
// One warp per query. Lane l -> channels [4l,4l+4), group g = l>>2.
// logit = 0.25*(u + beta + prq*Bg + prk*(Sq + 16*prq)) where
//   u (butterflied) = sum k_raw*q' + prq*sum k_raw,
//   beta = sum bk*q',  Bg = sum_{c in g} bk,  Sq = sum q' (group).
// out = sum_s w_s * v_raw + bv.
// ---------------------------------------------------------------------------
__global__ void __launch_bounds__(256) attn_kernel(
    const float* __restrict__ p, const float* __restrict__ p2,
    const int* __restrict__ idx,
    const float* __restrict__ bq, const float* __restrict__ bk,
    const float* __restrict__ bv,
    const float* __restrict__ W1, const float* __restrict__ b1,
    const float* __restrict__ bng, const float* __restrict__ bnb,
    const float* __restrict__ bnm, const float* __restrict__ bnv,
    const float* __restrict__ W2, const float* __restrict__ b2,
    float* __restrict__ out, int n)
{
    __shared__ float sA[9];
    __shared__ float sc[3];
    __shared__ float sW2[16][3];
    __shared__ float sb2[16];
    __shared__ float sBg[8];

    const int t = threadIdx.x;
    if (t < 9) {
        int r = t / 3;
        float s = bng[r] * rsqrtf(bnv[r] + 1e-5f);
        sA[t] = s * W1[t];
    }
    if (t < 3) sc[t] = bng[t] * rsqrtf(bnv[t] + 1e-5f) * (b1[t] - bnm[t]) + bnb[t];
    if (t < 48) sW2[t / 3][t % 3] = W2[t];
    if (t < 16) sb2[t] = b2[t];
    if (t < 8) {
        float s = 0.f;
#pragma unroll
        for (int c = 0; c < 16; c++) s += bk[t * 16 + c];
        sBg[t] = s;
    }
    __syncthreads();

    const int warp = t >> 5;
    const int lane = t & 31;
    const int i = blockIdx.x * 8 + warp;
    if (i >= n) return;

    const int g = lane >> 2;
    const float w2q0 = sW2[g][0], w2q1 = sW2[g][1], w2q2 = sW2[g][2], b2q = sb2[g];
    const float w2k0 = sW2[8 + g][0], w2k1 = sW2[8 + g][1], w2k2 = sW2[8 + g][2], b2k = sb2[8 + g];
    const float Bg = sBg[g];

    float4 q4 = *(const float4*)(g_q + (size_t)i * 128 + lane * 4);
    {
        const float4 bq4 = *(const float4*)(bq + lane * 4);
        q4.x += bq4.x; q4.y += bq4.y; q4.z += bq4.z; q4.w += bq4.w;
    }

    float qs, beta;
    {
        const float4 bk4 = *(const float4*)(bk + lane * 4);
        qs   = q4.x + q4.y + q4.z + q4.w;
        beta = bk4.x * q4.x + bk4.y * q4.y + bk4.z * q4.z + bk4.w * q4.w;
        qs   += __shfl_xor_sync(0xffffffffu, qs, 1);
        beta += __shfl_xor_sync(0xffffffffu, beta, 1);
        qs   += __shfl_xor_sync(0xffffffffu, qs, 2);
        beta += __shfl_xor_sync(0xffffffffu, beta, 2);
    }

    const float px = p[i * 3 + 0], py = p[i * 3 + 1], pz = p[i * 3 + 2];

    int nb[16];
    {
        const int4* ip = (const int4*)(idx + (size_t)i * 16);
#pragma unroll
        for (int s4 = 0; s4 < 4; s4++) {
            int4 v = ip[s4];
            nb[s4 * 4 + 0] = v.x; nb[s4 * 4 + 1] = v.y;
            nb[s4 * 4 + 2] = v.z; nb[s4 * 4 + 3] = v.w;
        }
    }

    float logit[16];
#pragma unroll
    for (int s = 0; s < 16; s++) {
        const int j = nb[s];
        const float4 k4 = *(const float4*)(g_k + (size_t)j * 128 + lane * 4);
        float kq = k4.x * q4.x + k4.y * q4.y + k4.z * q4.z + k4.w * q4.w;
        float ks = k4.x + k4.y + k4.z + k4.w;

        const float rx = p2[j * 3 + 0] - px;
        const float ry = p2[j * 3 + 1] - py;
        const float rz = p2[j * 3 + 2] - pz;
        const float h0 = fmaxf(sA[0] * rx + sA[1] * ry + sA[2] * rz + sc[0], 0.f);
        const float h1 = fmaxf(sA[3] * rx + sA[4] * ry + sA[5] * rz + sc[1], 0.f);
        const float h2 = fmaxf(sA[6] * rx + sA[7] * ry + sA[8] * rz + sc[2], 0.f);
        const float prq = w2q0 * h0 + w2q1 * h1 + w2q2 * h2 + b2q;
        const float prk = w2k0 * h0 + w2k1 * h1 + w2k2 * h2 + b2k;

        float u = fmaf(prq, ks, kq);
        u += __shfl_xor_sync(0xffffffffu, u, 1);
        u += __shfl_xor_sync(0xffffffffu, u, 2);

        logit[s] = 0.25f * (u + beta + prq * Bg + prk * fmaf(16.f, prq, qs));
    }

    float mx = logit[0];
#pragma unroll
    for (int s = 1; s < 16; s++) mx = fmaxf(mx, logit[s]);
    float denom = 0.f;
#pragma unroll
    for (int s = 0; s < 16; s++) {
        logit[s] = __expf(logit[s] - mx);
        denom += logit[s];
    }
    const float inv = 1.f / denom;

    float4 o = make_float4(0.f, 0.f, 0.f, 0.f);
#pragma unroll
    for (int s = 0; s < 16; s++) {
        const float w = logit[s] * inv;
        const float4 v4 = *(const float4*)(g_v + (size_t)nb[s] * 128 + lane * 4);
        o.x = fmaf(w, v4.x, o.x);
        o.y = fmaf(w, v4.y, o.y);
        o.z = fmaf(w, v4.z, o.z);
        o.w = fmaf(w, v4.w, o.w);
    }
    const float4 bv4 = *(const float4*)(bv + lane * 4);
    o.x += bv4.x; o.y += bv4.y; o.z += bv4.z; o.w += bv4.w;
    *(float4*)(out + (size_t)i * 128 + lane * 4) = o;
}

extern "C" void kernel_launch(void* const* d_in, const int* in_sizes, int n_in,
                              void* d_out, int out_size)
{
    const float* p   = (const float*)d_in[0];
    const float* x   = (const float*)d_in[1];
    const float* p2  = (const float*)d_in[2];
    const float* x2  = (const float*)d_in[3];
    const int*   idx = (const int*)d_in[4];
    const float* Wq  = (const float*)d_in[5];
    const float* bq  = (const float*)d_in[6];
    const float* Wk  = (const float*)d_in[7];
    const float* bk  = (const float*)d_in[8];
    const float* Wv  = (const float*)d_in[9];
    const float* bv  = (const float*)d_in[10];
    const float* W1  = (const float*)d_in[11];
    const float* b1  = (const float*)d_in[12];
    const float* bng = (const float*)d_in[13];
    const float* bnb = (const float*)d_in[14];
    const float* bnm = (const float*)d_in[15];
    const float* bnv = (const float*)d_in[16];
    const float* W2  = (const float*)d_in[17];
    const float* b2  = (const float*)d_in[18];
    float* out = (float*)d_out;

    const int n  = in_sizes[1] / NC;
    const int n2 = in_sizes[3] / NC;
    const int mmax = n > n2 ? n : n2;

    dim3 pg((mmax + 127) / 128, 3);
    proj_kernel<<<pg, 256>>>(x, x2, Wq, Wk, Wv, n, n2);
    attn_kernel<<<(n + 7) / 8, 256>>>(p, p2, idx, bq, bk, bv,
                                      W1, b1, bng, bnb, bnm, bnv,
                                      W2, b2, out, n);
}

// round 8
// speedup vs baseline: 1.2236x; 1.0579x over previous
#include <cuda_runtime.h>
#include <mma.h>

using namespace nvcuda;

#define NQ_MAX 50000
#define NC 128
#define NG 8
#define NS 16

// Padded by 128 rows: partial-tile wmma stores at the M edge write into the
// pad instead of the neighboring buffer.
__device__ float g_q[(NQ_MAX + 128) * NC];
__device__ float g_k[(NQ_MAX + 128) * NC];
__device__ float g_v[(NQ_MAX + 128) * NC];

__device__ __forceinline__ float to_tf32(float x) {
    float r;
    asm("cvt.rna.tf32.f32 %0, %1;" : "=f"(r) : "f"(x));
    return r;
}

// ---------------------------------------------------------------------------
// Projection GEMM (tf32 tensor cores): Y[m,c] = sum_k X[m,k] * W[c,k]
// Block tile 128x64, BK=32, 8 warps: 4(M) x 2(N), warp tile 32x32 (4 frags).
// Smaller accumulator footprint -> ~70 regs -> 3-4 CTA/SM for latency hiding.
// blockIdx.z = matrix (Q/K/V), blockIdx.y = N half.
// ---------------------------------------------------------------------------
#define LDA 36

__global__ void __launch_bounds__(256) proj_kernel(
    const float* __restrict__ x, const float* __restrict__ x2,
    const float* __restrict__ Wq, const float* __restrict__ Wk,
    const float* __restrict__ Wv,
    int n, int n2)
{
    const float *X, *W;
    float* Y;
    int M;
    if (blockIdx.z == 0)      { X = x;  W = Wq; Y = g_q; M = n;  }
    else if (blockIdx.z == 1) { X = x2; W = Wk; Y = g_k; M = n2; }
    else                      { X = x2; W = Wv; Y = g_v; M = n2; }

    __shared__ float As[128 * LDA];   // A[m][k], ld=LDA
    __shared__ float Bs[64 * LDA];    // Bs[c_local*LDA + k] = W[block_n+c][k]

    const int t = threadIdx.x;
    const int block_m = blockIdx.x * 128;
    const int block_n = blockIdx.y * 64;
    if (block_m >= M) return;

    const int warp = t >> 5;
    const int wm = (warp & 3) * 32;
    const int wn = (warp >> 2) * 32;

    wmma::fragment<wmma::accumulator, 16, 16, 8, float> acc[2][2];
#pragma unroll
    for (int i = 0; i < 2; i++)
#pragma unroll
        for (int j = 0; j < 2; j++) wmma::fill_fragment(acc[i][j], 0.0f);

    for (int k0 = 0; k0 < 128; k0 += 32) {
#pragma unroll
        for (int it = 0; it < 4; it++) {
            int lin = it * 256 + t;
            int r = lin >> 3;
            int c4 = (lin & 7) << 2;
            int gr = block_m + r;
            float4 xv = make_float4(0.f, 0.f, 0.f, 0.f);
            if (gr < M) xv = *(const float4*)(X + (size_t)gr * 128 + k0 + c4);
            As[r * LDA + c4 + 0] = to_tf32(xv.x);
            As[r * LDA + c4 + 1] = to_tf32(xv.y);
            As[r * LDA + c4 + 2] = to_tf32(xv.z);
            As[r * LDA + c4 + 3] = to_tf32(xv.w);
        }
#pragma unroll
        for (int it = 0; it < 2; it++) {
            int lin = it * 256 + t;
            int r = lin >> 3;          // 0..63
            int c4 = (lin & 7) << 2;
            float4 wv = *(const float4*)(W + (size_t)(block_n + r) * 128 + k0 + c4);
            Bs[r * LDA + c4 + 0] = to_tf32(wv.x);
            Bs[r * LDA + c4 + 1] = to_tf32(wv.y);
            Bs[r * LDA + c4 + 2] = to_tf32(wv.z);
            Bs[r * LDA + c4 + 3] = to_tf32(wv.w);
        }
        __syncthreads();

#pragma unroll
        for (int kk = 0; kk < 32; kk += 8) {
            wmma::fragment<wmma::matrix_a, 16, 16, 8, wmma::precision::tf32, wmma::row_major> a[2];
            wmma::fragment<wmma::matrix_b, 16, 16, 8, wmma::precision::tf32, wmma::col_major> b[2];
#pragma unroll
            for (int i = 0; i < 2; i++)
                wmma::load_matrix_sync(a[i], As + (wm + i * 16) * LDA + kk, LDA);
#pragma unroll
            for (int j = 0; j < 2; j++)
                wmma::load_matrix_sync(b[j], Bs + (wn + j * 16) * LDA + kk, LDA);
#pragma unroll
            for (int i = 0; i < 2; i++)
#pragma unroll
                for (int j = 0; j < 2; j++)
                    wmma::mma_sync(acc[i][j], a[i], b[j], acc[i][j]);
        }
        __syncthreads();
    }

#pragma unroll
    for (int i = 0; i < 2; i++)
#pragma unroll
        for (int j = 0; j < 2; j++)
            wmma::store_matrix_sync(
                Y + (size_t)(block_m + wm + i * 16) * 128 + block_n + wn + j * 16,
                acc[i][j], 128, wmma::mem_row_major);
}

// ---------------------------------------------------------------------------
// Fused gather + positional MLP + grouped attention.
// HALF-WARP per query: sub = lane>>4 selects query, ll = lane&15.
// Lane ll owns channels [ll*8, ll*8+8); group g = ll>>1 (2 lanes/group).
// Group reduction = ONE shfl_xor(1). Every warp instruction serves 2 queries.
// logit = 0.25*(u + beta + prq*Bg + prk*(qs + 16*prq)),
//   u (pair-butterflied) = sum k_raw*q' + prq*sum k_raw
//   beta = sum bk*q' (group), Bg = sum bk (group), qs = sum q' (group)
// out = sum_s w_s * v_raw + bv.
// ---------------------------------------------------------------------------
__global__ void __launch_bounds__(256) attn_kernel(
    const float* __restrict__ p, const float* __restrict__ p2,
    const int* __restrict__ idx,
    const float* __restrict__ bq, const float* __restrict__ bk,
    const float* __restrict__ bv,
    const float* __restrict__ W1, const float* __restrict__ b1,
    const float* __restrict__ bng, const float* __restrict__ bnb,
    const float* __restrict__ bnm, const float* __restrict__ bnv,
    const float* __restrict__ W2, const float* __restrict__ b2,
    float* __restrict__ out, int n)
{
    __shared__ float sA[9];
    __shared__ float sc[3];
    __shared__ float sW2[16][3];
    __shared__ float sb2[16];
    __shared__ float sBg[8];

    const int t = threadIdx.x;
    if (t < 9) {
        int r = t / 3;
        float s = bng[r] * rsqrtf(bnv[r] + 1e-5f);
        sA[t] = s * W1[t];
    }
    if (t < 3) sc[t] = bng[t] * rsqrtf(bnv[t] + 1e-5f) * (b1[t] - bnm[t]) + bnb[t];
    if (t < 48) sW2[t / 3][t % 3] = W2[t];
    if (t < 16) sb2[t] = b2[t];
    if (t < 8) {
        float s = 0.f;
#pragma unroll
        for (int c = 0; c < 16; c++) s += bk[t * 16 + c];
        sBg[t] = s;
    }
    __syncthreads();

    const int warp = t >> 5;
    const int lane = t & 31;
    const int sub = lane >> 4;
    const int ll = lane & 15;
    const int qa = blockIdx.x * 16 + warp * 2 + sub;
    const int i = qa < n ? qa : (n - 1);   // clamp; write guarded below

    const int g = ll >> 1;
    const float w2q0 = sW2[g][0], w2q1 = sW2[g][1], w2q2 = sW2[g][2], b2q = sb2[g];
    const float w2k0 = sW2[8 + g][0], w2k1 = sW2[8 + g][1], w2k2 = sW2[8 + g][2], b2k = sb2[8 + g];
    const float Bg = sBg[g];

    // q' = q_raw + bq for this lane's 8 channels
    float4 q0, q1;
    {
        const float4* qp  = (const float4*)(g_q + (size_t)i * 128 + ll * 8);
        const float4* bqp = (const float4*)(bq + ll * 8);
        q0 = qp[0]; q1 = qp[1];
        float4 b0 = bqp[0], b1v = bqp[1];
        q0.x += b0.x; q0.y += b0.y; q0.z += b0.z; q0.w += b0.w;
        q1.x += b1v.x; q1.y += b1v.y; q1.z += b1v.z; q1.w += b1v.w;
    }

    float qs, beta;
    {
        const float4* bkp = (const float4*)(bk + ll * 8);
        const float4 k0 = bkp[0], k1 = bkp[1];
        qs   = (q0.x + q0.y + q0.z + q0.w) + (q1.x + q1.y + q1.z + q1.w);
        beta = k0.x * q0.x + k0.y * q0.y + k0.z * q0.z + k0.w * q0.w
             + k1.x * q1.x + k1.y * q1.y + k1.z * q1.z + k1.w * q1.w;
        qs   += __shfl_xor_sync(0xffffffffu, qs, 1);
        beta += __shfl_xor_sync(0xffffffffu, beta, 1);
    }

    const float px = p[i * 3 + 0], py = p[i * 3 + 1], pz = p[i * 3 + 2];

    int nb[16];
    {
        const int4* ip = (const int4*)(idx + (size_t)i * 16);
#pragma unroll
        for (int s4 = 0; s4 < 4; s4++) {
            int4 v = ip[s4];
            nb[s4 * 4 + 0] = v.x; nb[s4 * 4 + 1] = v.y;
            nb[s4 * 4 + 2] = v.z; nb[s4 * 4 + 3] = v.w;
        }
    }

    float logit[16];
#pragma unroll
    for (int s = 0; s < 16; s++) {
        const int j = nb[s];
        const float4* kp = (const float4*)(g_k + (size_t)j * 128 + ll * 8);
        const float4 k0 = kp[0], k1 = kp[1];
        float kq = k0.x * q0.x + k0.y * q0.y + k0.z * q0.z + k0.w * q0.w
                 + k1.x * q1.x + k1.y * q1.y + k1.z * q1.z + k1.w * q1.w;
        float ks = (k0.x + k0.y + k0.z + k0.w) + (k1.x + k1.y + k1.z + k1.w);

        const float rx = p2[j * 3 + 0] - px;
        const float ry = p2[j * 3 + 1] - py;
        const float rz = p2[j * 3 + 2] - pz;
        const float h0 = fmaxf(sA[0] * rx + sA[1] * ry + sA[2] * rz + sc[0], 0.f);
        const float h1 = fmaxf(sA[3] * rx + sA[4] * ry + sA[5] * rz + sc[1], 0.f);
        const float h2 = fmaxf(sA[6] * rx + sA[7] * ry + sA[8] * rz + sc[2], 0.f);
        const float prq = w2q0 * h0 + w2q1 * h1 + w2q2 * h2 + b2q;
        const float prk = w2k0 * h0 + w2k1 * h1 + w2k2 * h2 + b2k;

        float u = fmaf(prq, ks, kq);
        u += __shfl_xor_sync(0xffffffffu, u, 1);

        logit[s] = 0.25f * (u + beta + prq * Bg + prk * fmaf(16.f, prq, qs));
    }

    float mx = logit[0];
#pragma unroll
    for (int s = 1; s < 16; s++) mx = fmaxf(mx, logit[s]);
    float denom = 0.f;
#pragma unroll
    for (int s = 0; s < 16; s++) {
        logit[s] = __expf(logit[s] - mx);
        denom += logit[s];
    }
    const float inv = 1.f / denom;

    float4 o0 = make_float4(0.f, 0.f, 0.f, 0.f);
    float4 o1 = make_float4(0.f, 0.f, 0.f, 0.f);
#pragma unroll
    for (int s = 0; s < 16; s++) {
        const float w = logit[s] * inv;
        const float4* vp = (const float4*)(g_v + (size_t)nb[s] * 128 + ll * 8);
        const float4 v0 = vp[0], v1 = vp[1];
        o0.x = fmaf(w, v0.x, o0.x); o0.y = fmaf(w, v0.y, o0.y);
        o0.z = fmaf(w, v0.z, o0.z); o0.w = fmaf(w, v0.w, o0.w);
        o1.x = fmaf(w, v1.x, o1.x); o1.y = fmaf(w, v1.y, o1.y);
        o1.z = fmaf(w, v1.z, o1.z); o1.w = fmaf(w, v1.w, o1.w);
    }

    if (qa < n) {
        const float4* bvp = (const float4*)(bv + ll * 8);
        const float4 b0 = bvp[0], b1v = bvp[1];
        o0.x += b0.x; o0.y += b0.y; o0.z += b0.z; o0.w += b0.w;
        o1.x += b1v.x; o1.y += b1v.y; o1.z += b1v.z; o1.w += b1v.w;
        float4* op = (float4*)(out + (size_t)qa * 128 + ll * 8);
        op[0] = o0;
        op[1] = o1;
    }
}

extern "C" void kernel_launch(void* const* d_in, const int* in_sizes, int n_in,
                              void* d_out, int out_size)
{
    const float* p   = (const float*)d_in[0];
    const float* x   = (const float*)d_in[1];
    const float* p2  = (const float*)d_in[2];
    const float* x2  = (const float*)d_in[3];
    const int*   idx = (const int*)d_in[4];
    const float* Wq  = (const float*)d_in[5];
    const float* bq  = (const float*)d_in[6];
    const float* Wk  = (const float*)d_in[7];
    const float* bk  = (const float*)d_in[8];
    const float* Wv  = (const float*)d_in[9];
    const float* bv  = (const float*)d_in[10];
    const float* W1  = (const float*)d_in[11];
    const float* b1  = (const float*)d_in[12];
    const float* bng = (const float*)d_in[13];
    const float* bnb = (const float*)d_in[14];
    const float* bnm = (const float*)d_in[15];
    const float* bnv = (const float*)d_in[16];
    const float* W2  = (const float*)d_in[17];
    const float* b2  = (const float*)d_in[18];
    float* out = (float*)d_out;

    const int n  = in_sizes[1] / NC;
    const int n2 = in_sizes[3] / NC;
    const int mmax = n > n2 ? n : n2;

    dim3 pg((mmax + 127) / 128, 2, 3);
    proj_kernel<<<pg, 256>>>(x, x2, Wq, Wk, Wv, n, n2);
    attn_kernel<<<(n + 15) / 16, 256>>>(p, p2, idx, bq, bk, bv,
                                        W1, b1, bng, bnb, bnm, bnv,
                                        W2, b2, out, n);
}

// round 9
// speedup vs baseline: 1.3738x; 1.1227x over previous
#include <cuda_runtime.h>
#include <mma.h>

using namespace nvcuda;

#define NQ_MAX 50000
#define NC 128
#define NG 8
#define NS 16

// Padded by 128 rows: partial-tile wmma stores at the M edge write into the
// pad instead of the neighboring buffer.
__device__ float g_q[(NQ_MAX + 128) * NC];
__device__ float g_k[(NQ_MAX + 128) * NC];
__device__ float g_v[(NQ_MAX + 128) * NC];

__device__ __forceinline__ float to_tf32(float x) {
    float r;
    asm("cvt.rna.tf32.f32 %0, %1;" : "=f"(r) : "f"(x));
    return r;
}

// ---------------------------------------------------------------------------
// Projection GEMM (tf32 tensor cores) — R4 version (known 71us).
// Y[m,c] = sum_k X[m,k] * W[c,k]   (biases folded into attn kernel)
// Block tile 128x128, BK=32, 8 warps: 4(M) x 2(N), warp tile 32x64.
// ---------------------------------------------------------------------------
#define LDA 36

__global__ void __launch_bounds__(256) proj_kernel(
    const float* __restrict__ x, const float* __restrict__ x2,
    const float* __restrict__ Wq, const float* __restrict__ Wk,
    const float* __restrict__ Wv,
    int n, int n2)
{
    const float *X, *W;
    float* Y;
    int M;
    if (blockIdx.y == 0)      { X = x;  W = Wq; Y = g_q; M = n;  }
    else if (blockIdx.y == 1) { X = x2; W = Wk; Y = g_k; M = n2; }
    else                      { X = x2; W = Wv; Y = g_v; M = n2; }

    __shared__ float As[128 * LDA];
    __shared__ float Bs[128 * LDA];

    const int t = threadIdx.x;
    const int block_m = blockIdx.x * 128;
    if (block_m >= M) return;

    const int warp = t >> 5;
    const int wm = (warp & 3) * 32;
    const int wn = (warp >> 2) * 64;

    wmma::fragment<wmma::accumulator, 16, 16, 8, float> acc[2][4];
#pragma unroll
    for (int i = 0; i < 2; i++)
#pragma unroll
        for (int j = 0; j < 4; j++) wmma::fill_fragment(acc[i][j], 0.0f);

    for (int k0 = 0; k0 < 128; k0 += 32) {
#pragma unroll
        for (int it = 0; it < 4; it++) {
            int lin = it * 256 + t;
            int r = lin >> 3;
            int c4 = (lin & 7) << 2;
            int gr = block_m + r;
            float4 xv = make_float4(0.f, 0.f, 0.f, 0.f);
            if (gr < M) xv = *(const float4*)(X + (size_t)gr * 128 + k0 + c4);
            As[r * LDA + c4 + 0] = to_tf32(xv.x);
            As[r * LDA + c4 + 1] = to_tf32(xv.y);
            As[r * LDA + c4 + 2] = to_tf32(xv.z);
            As[r * LDA + c4 + 3] = to_tf32(xv.w);
            float4 wv = *(const float4*)(W + (size_t)r * 128 + k0 + c4);
            Bs[r * LDA + c4 + 0] = to_tf32(wv.x);
            Bs[r * LDA + c4 + 1] = to_tf32(wv.y);
            Bs[r * LDA + c4 + 2] = to_tf32(wv.z);
            Bs[r * LDA + c4 + 3] = to_tf32(wv.w);
        }
        __syncthreads();

#pragma unroll
        for (int kk = 0; kk < 32; kk += 8) {
            wmma::fragment<wmma::matrix_a, 16, 16, 8, wmma::precision::tf32, wmma::row_major> a[2];
            wmma::fragment<wmma::matrix_b, 16, 16, 8, wmma::precision::tf32, wmma::col_major> b[4];
#pragma unroll
            for (int i = 0; i < 2; i++)
                wmma::load_matrix_sync(a[i], As + (wm + i * 16) * LDA + kk, LDA);
#pragma unroll
            for (int j = 0; j < 4; j++)
                wmma::load_matrix_sync(b[j], Bs + (wn + j * 16) * LDA + kk, LDA);
#pragma unroll
            for (int i = 0; i < 2; i++)
#pragma unroll
                for (int j = 0; j < 4; j++)
                    wmma::mma_sync(acc[i][j], a[i], b[j], acc[i][j]);
        }
        __syncthreads();
    }

#pragma unroll
    for (int i = 0; i < 2; i++)
#pragma unroll
        for (int j = 0; j < 4; j++)
            wmma::store_matrix_sync(
                Y + (size_t)(block_m + wm + i * 16) * 128 + wn + j * 16,
                acc[i][j], 128, wmma::mem_row_major);
}

// ---------------------------------------------------------------------------
// Fused gather + positional MLP + grouped attention.
// One warp per query (R4 memory layout). Lane l -> channels [4l,4l+4),
// group g = l>>2.
// NEW: the neighbor MLP hidden (h0,h1,h2) is group-independent, so lane l
// computes it ONCE for neighbor (l&15); the main loop fetches it with 3
// shfls instead of recomputing (p2 gather + 12-op MLP) per neighbor.
// logit = 0.25*(u + beta + prq*Bg + prk*(qs + 16*prq)),
//   u (butterflied) = sum k_raw*q' + prq*sum k_raw,
//   beta = sum bk*q', Bg = sum_{c in g} bk, qs = sum q' (group).
// out = sum_s w_s * v_raw + bv.
// ---------------------------------------------------------------------------
__global__ void __launch_bounds__(256) attn_kernel(
    const float* __restrict__ p, const float* __restrict__ p2,
    const int* __restrict__ idx,
    const float* __restrict__ bq, const float* __restrict__ bk,
    const float* __restrict__ bv,
    const float* __restrict__ W1, const float* __restrict__ b1,
    const float* __restrict__ bng, const float* __restrict__ bnb,
    const float* __restrict__ bnm, const float* __restrict__ bnv,
    const float* __restrict__ W2, const float* __restrict__ b2,
    float* __restrict__ out, int n)
{
    __shared__ float sA[9];
    __shared__ float sc[3];
    __shared__ float sW2[16][3];
    __shared__ float sb2[16];
    __shared__ float sBg[8];

    const int t = threadIdx.x;
    if (t < 9) {
        int r = t / 3;
        float s = bng[r] * rsqrtf(bnv[r] + 1e-5f);
        sA[t] = s * W1[t];
    }
    if (t < 3) sc[t] = bng[t] * rsqrtf(bnv[t] + 1e-5f) * (b1[t] - bnm[t]) + bnb[t];
    if (t < 48) sW2[t / 3][t % 3] = W2[t];
    if (t < 16) sb2[t] = b2[t];
    if (t < 8) {
        float s = 0.f;
#pragma unroll
        for (int c = 0; c < 16; c++) s += bk[t * 16 + c];
        sBg[t] = s;
    }
    __syncthreads();

    const int warp = t >> 5;
    const int lane = t & 31;
    const int i = blockIdx.x * 8 + warp;
    if (i >= n) return;

    const int g = lane >> 2;
    const float w2q0 = sW2[g][0], w2q1 = sW2[g][1], w2q2 = sW2[g][2], b2q = sb2[g];
    const float w2k0 = sW2[8 + g][0], w2k1 = sW2[8 + g][1], w2k2 = sW2[8 + g][2], b2k = sb2[8 + g];
    const float Bg = sBg[g];

    float4 q4 = *(const float4*)(g_q + (size_t)i * 128 + lane * 4);
    {
        const float4 bq4 = *(const float4*)(bq + lane * 4);
        q4.x += bq4.x; q4.y += bq4.y; q4.z += bq4.z; q4.w += bq4.w;
    }

    float qs, beta;
    {
        const float4 bk4 = *(const float4*)(bk + lane * 4);
        qs   = q4.x + q4.y + q4.z + q4.w;
        beta = bk4.x * q4.x + bk4.y * q4.y + bk4.z * q4.z + bk4.w * q4.w;
        qs   += __shfl_xor_sync(0xffffffffu, qs, 1);
        beta += __shfl_xor_sync(0xffffffffu, beta, 1);
        qs   += __shfl_xor_sync(0xffffffffu, qs, 2);
        beta += __shfl_xor_sync(0xffffffffu, beta, 2);
    }

    int nb[16];
    {
        const int4* ip = (const int4*)(idx + (size_t)i * 16);
#pragma unroll
        for (int s4 = 0; s4 < 4; s4++) {
            int4 v = ip[s4];
            nb[s4 * 4 + 0] = v.x; nb[s4 * 4 + 1] = v.y;
            nb[s4 * 4 + 2] = v.z; nb[s4 * 4 + 3] = v.w;
        }
    }

    // --- per-neighbor MLP hidden, computed once by lane (l & 15) ---
    float h0, h1, h2;
    {
        const float px = p[i * 3 + 0], py = p[i * 3 + 1], pz = p[i * 3 + 2];
        const int jm = nb[lane & 15];
        const float rx = p2[jm * 3 + 0] - px;
        const float ry = p2[jm * 3 + 1] - py;
        const float rz = p2[jm * 3 + 2] - pz;
        h0 = fmaxf(fmaf(sA[0], rx, fmaf(sA[1], ry, fmaf(sA[2], rz, sc[0]))), 0.f);
        h1 = fmaxf(fmaf(sA[3], rx, fmaf(sA[4], ry, fmaf(sA[5], rz, sc[1]))), 0.f);
        h2 = fmaxf(fmaf(sA[6], rx, fmaf(sA[7], ry, fmaf(sA[8], rz, sc[2]))), 0.f);
    }

    float logit[16];
#pragma unroll
    for (int s = 0; s < 16; s++) {
        const int j = nb[s];
        const float4 k4 = *(const float4*)(g_k + (size_t)j * 128 + lane * 4);
        float kq = k4.x * q4.x + k4.y * q4.y + k4.z * q4.z + k4.w * q4.w;
        float ks = k4.x + k4.y + k4.z + k4.w;

        const float h0s = __shfl_sync(0xffffffffu, h0, s);
        const float h1s = __shfl_sync(0xffffffffu, h1, s);
        const float h2s = __shfl_sync(0xffffffffu, h2, s);
        const float prq = fmaf(w2q0, h0s, fmaf(w2q1, h1s, fmaf(w2q2, h2s, b2q)));
        const float prk = fmaf(w2k0, h0s, fmaf(w2k1, h1s, fmaf(w2k2, h2s, b2k)));

        float u = fmaf(prq, ks, kq);
        u += __shfl_xor_sync(0xffffffffu, u, 1);
        u += __shfl_xor_sync(0xffffffffu, u, 2);

        logit[s] = 0.25f * (u + beta + prq * Bg + prk * fmaf(16.f, prq, qs));
    }

    float mx = logit[0];
#pragma unroll
    for (int s = 1; s < 16; s++) mx = fmaxf(mx, logit[s]);
    float denom = 0.f;
#pragma unroll
    for (int s = 0; s < 16; s++) {
        logit[s] = __expf(logit[s] - mx);
        denom += logit[s];
    }
    const float inv = 1.f / denom;

    float4 o = make_float4(0.f, 0.f, 0.f, 0.f);
#pragma unroll
    for (int s = 0; s < 16; s++) {
        const float w = logit[s] * inv;
        const float4 v4 = *(const float4*)(g_v + (size_t)nb[s] * 128 + lane * 4);
        o.x = fmaf(w, v4.x, o.x);
        o.y = fmaf(w, v4.y, o.y);
        o.z = fmaf(w, v4.z, o.z);
        o.w = fmaf(w, v4.w, o.w);
    }
    const float4 bv4 = *(const float4*)(bv + lane * 4);
    o.x += bv4.x; o.y += bv4.y; o.z += bv4.z; o.w += bv4.w;
    *(float4*)(out + (size_t)i * 128 + lane * 4) = o;
}

extern "C" void kernel_launch(void* const* d_in, const int* in_sizes, int n_in,
                              void* d_out, int out_size)
{
    const float* p   = (const float*)d_in[0];
    const float* x   = (const float*)d_in[1];
    const float* p2  = (const float*)d_in[2];
    const float* x2  = (const float*)d_in[3];
    const int*   idx = (const int*)d_in[4];
    const float* Wq  = (const float*)d_in[5];
    const float* bq  = (const float*)d_in[6];
    const float* Wk  = (const float*)d_in[7];
    const float* bk  = (const float*)d_in[8];
    const float* Wv  = (const float*)d_in[9];
    const float* bv  = (const float*)d_in[10];
    const float* W1  = (const float*)d_in[11];
    const float* b1  = (const float*)d_in[12];
    const float* bng = (const float*)d_in[13];
    const float* bnb = (const float*)d_in[14];
    const float* bnm = (const float*)d_in[15];
    const float* bnv = (const float*)d_in[16];
    const float* W2  = (const float*)d_in[17];
    const float* b2  = (const float*)d_in[18];
    float* out = (float*)d_out;

    const int n  = in_sizes[1] / NC;
    const int n2 = in_sizes[3] / NC;
    const int mmax = n > n2 ? n : n2;

    dim3 pg((mmax + 127) / 128, 3);
    proj_kernel<<<pg, 256>>>(x, x2, Wq, Wk, Wv, n, n2);
    attn_kernel<<<(n + 7) / 8, 256>>>(p, p2, idx, bq, bk, bv,
                                      W1, b1, bng, bnb, bnm, bnv,
                                      W2, b2, out, n);
}